// round 15
// baseline (speedup 1.0000x reference)
#include <cuda_runtime.h>
#include <math.h>

// Fixed shapes: features [16,512,768] f32, labels [16,512] i32. N = 8192.
#define H      768
#define NCLS   10
#define TPB    512
#define NBLK   256              // 2 blocks/SM, 32 warps/SM
#define RPB    32               // rows per block (N = NBLK*RPB = 8192)
#define RPW    2                // rows per warp (16 warps * 2 = 32)
#define CH     (NCLS * H)       // 7680 floats
#define CH4    (CH / 4)         // 1920 float4
#define TEMPERATURE 0.07f
#define EPS    1e-12f

// Device scratch. Zero at module load; restored to zero by the last block
// every run (self-cleaning for graph replay).
__device__ float    g_cs[CH];       // global class sums (vector-RED target)
__device__ int      g_cnt_tot[NCLS];
__device__ unsigned g_done = 0;

// Vector reduction: one RED.F32x4 to global memory (sm_90+).
__device__ __forceinline__ void red_add_v4(float* addr, float4 v)
{
    asm volatile("red.global.add.v4.f32 [%0], {%1, %2, %3, %4};"
                 :: "l"(addr), "f"(v.x), "f"(v.y), "f"(v.z), "f"(v.w)
                 : "memory");
}

// ---------------------------------------------------------------------------
// Single-pass kernel: each warp loads its rows ONCE, computes the norm via
// butterfly shuffles (all lanes get the sum -> no smem round-trip), and
// accumulates the normalized row into acc[class] with smem atomics.
// Then RED.F32x4 flush into g_cs; last block runs the f32 epilogue.
// ---------------------------------------------------------------------------
__global__ __launch_bounds__(TPB, 2) void supcon_all(
    const float* __restrict__ feat,
    const int*   __restrict__ labels,
    float*       __restrict__ out,
    int out_size, int N)
{
    __shared__ float acc[CH];       // 30720 B
    __shared__ int   labs[RPB];
    __shared__ unsigned ticket_sh;
    __shared__ float sredA[16];
    __shared__ float sredP[16];
    __shared__ float loss_sh;

    const int tid  = threadIdx.x;
    const int lane = tid & 31;
    const int warp = tid >> 5;
    const int bid  = blockIdx.x;
    const int row0 = bid * RPB;

    for (int i = tid; i < CH; i += TPB) acc[i] = 0.0f;
    if (tid < RPB) {
        int l = labels[row0 + tid];
        labs[tid] = min(max(l, 0), NCLS - 1);
    }
    __syncthreads();

    // ---- Single pass: load row, norm (warp-local), smem-atomic accumulate ----
    #pragma unroll
    for (int rr = 0; rr < RPW; ++rr) {
        const int r = warp * RPW + rr;
        const float4* x4 = reinterpret_cast<const float4*>(
                               feat + (size_t)(row0 + r) * H);
        float4 v[6];
        #pragma unroll
        for (int j = 0; j < 6; ++j)          // 6 independent LDG.128
            v[j] = x4[j * 32 + lane];

        float ss = 0.0f;
        #pragma unroll
        for (int j = 0; j < 6; ++j)
            ss += v[j].x*v[j].x + v[j].y*v[j].y + v[j].z*v[j].z + v[j].w*v[j].w;
        #pragma unroll
        for (int o = 16; o > 0; o >>= 1)     // butterfly: ALL lanes get sum
            ss += __shfl_xor_sync(0xffffffffu, ss, o);
        const float iv = 1.0f / fmaxf(sqrtf(ss), EPS);

        float* a = acc + labs[r] * H;
        #pragma unroll
        for (int j = 0; j < 6; ++j) {
            float* p = a + j * 128 + lane * 4;
            atomicAdd(p + 0, v[j].x * iv);
            atomicAdd(p + 1, v[j].y * iv);
            atomicAdd(p + 2, v[j].z * iv);
            atomicAdd(p + 3, v[j].w * iv);
        }
    }
    __syncthreads();

    // ---- Flush: vector reductions straight into g_cs ----
    {
        const float4* a4 = reinterpret_cast<const float4*>(acc);
        #pragma unroll
        for (int k = 0; k < 4; ++k) {
            const int i = k * TPB + tid;    // [0, 2048); CH4 = 1920
            if (i < CH4)
                red_add_v4(g_cs + 4 * i, a4[i]);
        }
        if (tid < NCLS) {
            int c = 0;
            #pragma unroll
            for (int r = 0; r < RPB; ++r) c += (labs[r] == tid);
            if (c > 0) atomicAdd(&g_cnt_tot[tid], c);
        }
    }

    // ---- Last-block ticket (no spinning) ----
    __threadfence();
    __syncthreads();
    if (tid == 0) ticket_sh = atomicAdd(&g_done, 1u);
    __syncthreads();
    if (ticket_sh != NBLK - 1) return;
    __threadfence();   // acquire: all other blocks' REDs visible

    // ---- Epilogue (f32) ----
    float p_all = 0.0f, p_pos = 0.0f;
    for (int h = tid; h < H; h += TPB) {
        float sh = 0.0f;
        #pragma unroll
        for (int c = 0; c < NCLS; ++c) {
            float vv = g_cs[c * H + h];
            sh    += vv;
            p_pos += vv * vv;
        }
        p_all += sh * sh;
    }
    #pragma unroll
    for (int o = 16; o > 0; o >>= 1) {
        p_all += __shfl_xor_sync(0xffffffffu, p_all, o);
        p_pos += __shfl_xor_sync(0xffffffffu, p_pos, o);
    }
    if (lane == 0) { sredA[warp] = p_all; sredP[warp] = p_pos; }
    __syncthreads();

    if (tid == 0) {
        float A = 0.0f, P = 0.0f;
        #pragma unroll
        for (int w = 0; w < 16; ++w) { A += sredA[w]; P += sredP[w]; }
        float n_pos = 0.0f;
        #pragma unroll
        for (int c = 0; c < NCLS; ++c) {
            float nc = (float)g_cnt_tot[c];
            n_pos += nc * nc;
        }
        float Nf    = (float)N;
        float n_neg = Nf * Nf - n_pos;

        float pos_mean = (P / TEMPERATURE) / n_pos;
        float neg_mean = ((A - P) / TEMPERATURE) / n_neg;
        float d = neg_mean - pos_mean;
        loss_sh = (d > 0.0f) ? d + log1pf(expf(-d)) : log1pf(expf(d));
    }
    __syncthreads();
    for (int i = tid; i < out_size; i += TPB) out[i] = loss_sh;

    // Self-clean for the next graph replay.
    for (int i = tid; i < CH; i += TPB) g_cs[i] = 0.0f;
    if (tid < NCLS) g_cnt_tot[tid] = 0;
    if (tid == 0)   g_done = 0u;
}

// ---------------------------------------------------------------------------
extern "C" void kernel_launch(void* const* d_in, const int* in_sizes, int n_in,
                              void* d_out, int out_size)
{
    const float* feat   = (const float*)d_in[0];
    const int*   labels = (const int*)d_in[1];
    float*       out    = (float*)d_out;
    const int N = in_sizes[1];   // 8192

    supcon_all<<<NBLK, TPB>>>(feat, labels, out, out_size, N);
}

// round 16
// speedup vs baseline: 1.3788x; 1.3788x over previous
#include <cuda_runtime.h>
#include <math.h>

// Fixed shapes: features [16,512,768] f32, labels [16,512] i32. N = 8192.
#define H      768
#define H2     (H / 2)          // 384 float2 per row
#define NCLS   10
#define TPB    512
#define NBLK   256              // 2 blocks/SM co-resident (grid 1.73/SM avg)
#define RPB    32               // rows per block (N = NBLK*RPB = 8192)
#define RPW    2                // rows per warp in phase A (16 warps * 2)
#define CH     (NCLS * H)       // 7680 floats
#define CH4    (CH / 4)         // 1920 float4
#define TEMPERATURE 0.07f
#define EPS    1e-12f

// Device scratch. Zero at module load; restored to zero by the last block
// every run (self-cleaning for graph replay).
__device__ float    g_cs[CH];       // global class sums (vector-RED target)
__device__ int      g_cnt_tot[NCLS];
__device__ unsigned g_done = 0;

// Vector reduction: one RED.F32x4 to global memory (sm_90+).
__device__ __forceinline__ void red_add_v4(float* addr, float4 v)
{
    asm volatile("red.global.add.v4.f32 [%0], {%1, %2, %3, %4};"
                 :: "l"(addr), "f"(v.x), "f"(v.y), "f"(v.z), "f"(v.w)
                 : "memory");
}

// ---------------------------------------------------------------------------
// Kernel: Phase A warp-local norms (+ warp 0 counting-sorts rows by label),
// Phase B class-sorted register accumulation with plain STS (no RMW, no LDS,
// no acc zeroing), RED.F32x4 flush, last-block f32 epilogue.
// ---------------------------------------------------------------------------
__global__ __launch_bounds__(TPB, 2) void supcon_all(
    const float* __restrict__ feat,
    const int*   __restrict__ labels,
    float*       __restrict__ out,
    int out_size, int N)
{
    __shared__ float acc[CH];       // 30720 B (fully overwritten in phase B)
    __shared__ float inv[RPB];
    __shared__ int   labs[RPB];
    __shared__ int   order[RPB];    // rows sorted by label
    __shared__ int   start[NCLS + 1];
    __shared__ unsigned ticket_sh;
    __shared__ float sredA[16];
    __shared__ float sredP[16];
    __shared__ float loss_sh;

    const int tid  = threadIdx.x;
    const int lane = tid & 31;
    const int warp = tid >> 5;
    const int bid  = blockIdx.x;
    const int row0 = bid * RPB;

    // Warp 0 lanes load labels (parallel), before its phase A work.
    if (warp == 0) {
        int l = labels[row0 + lane];
        labs[lane] = min(max(l, 0), NCLS - 1);
    }

    // ---- Phase A: each of 16 warps computes norms of its 2 rows ----
    #pragma unroll
    for (int rr = 0; rr < RPW; ++rr) {
        const int r = warp * RPW + rr;
        const float4* x4 = reinterpret_cast<const float4*>(
                               feat + (size_t)(row0 + r) * H);
        float4 v[6];
        #pragma unroll
        for (int j = 0; j < 6; ++j)          // 6 independent LDG.128
            v[j] = x4[j * 32 + lane];
        float ss = 0.0f;
        #pragma unroll
        for (int j = 0; j < 6; ++j)
            ss += v[j].x*v[j].x + v[j].y*v[j].y + v[j].z*v[j].z + v[j].w*v[j].w;
        #pragma unroll
        for (int o = 16; o > 0; o >>= 1)
            ss += __shfl_xor_sync(0xffffffffu, ss, o);
        if (lane == 0)
            inv[r] = 1.0f / fmaxf(sqrtf(ss), EPS);
    }

    // Warp 0 lane 0: counting sort of the 32 rows by label (~100 cycles,
    // overlapped with the other warps' phase A).
    if (warp == 0) {
        __syncwarp();
        if (lane == 0) {
            int cnt[NCLS];
            #pragma unroll
            for (int c = 0; c < NCLS; ++c) cnt[c] = 0;
            #pragma unroll
            for (int r = 0; r < RPB; ++r) cnt[labs[r]]++;
            int s = 0;
            #pragma unroll
            for (int c = 0; c < NCLS; ++c) { start[c] = s; s += cnt[c]; }
            start[NCLS] = s;   // == RPB
            int pos[NCLS];
            #pragma unroll
            for (int c = 0; c < NCLS; ++c) pos[c] = start[c];
            #pragma unroll
            for (int r = 0; r < RPB; ++r) order[pos[labs[r]]++] = r;
        }
    }
    __syncthreads();

    // ---- Phase B: class-sorted register accumulation, plain STS.64 ----
    if (tid < H2) {
        float2* ap = reinterpret_cast<float2*>(acc);
        #pragma unroll
        for (int c = 0; c < NCLS; ++c) {
            float2 s = make_float2(0.0f, 0.0f);
            const int k0 = start[c], k1 = start[c + 1];
            for (int k = k0; k < k1; ++k) {
                const int r = order[k];
                float2 v = reinterpret_cast<const float2*>(
                               feat + (size_t)(row0 + r) * H)[tid];
                const float iv = inv[r];
                s.x += v.x * iv;
                s.y += v.y * iv;
            }
            ap[c * H2 + tid] = s;      // exactly one plain store per class
        }
    }
    // Class counts from the sort (free).
    if (tid < NCLS) {
        int c = start[tid + 1] - start[tid];
        if (c > 0) atomicAdd(&g_cnt_tot[tid], c);
    }
    __syncthreads();

    // ---- Flush: vector reductions straight into g_cs ----
    {
        const float4* a4 = reinterpret_cast<const float4*>(acc);
        #pragma unroll
        for (int k = 0; k < 4; ++k) {
            const int i = k * TPB + tid;    // [0, 2048); CH4 = 1920
            if (i < CH4)
                red_add_v4(g_cs + 4 * i, a4[i]);
        }
    }

    // ---- Last-block ticket (no spinning) ----
    __threadfence();
    __syncthreads();
    if (tid == 0) ticket_sh = atomicAdd(&g_done, 1u);
    __syncthreads();
    if (ticket_sh != NBLK - 1) return;
    __threadfence();   // acquire: all other blocks' REDs visible

    // ---- Epilogue (f32) ----
    float p_all = 0.0f, p_pos = 0.0f;
    for (int h = tid; h < H; h += TPB) {
        float sh = 0.0f;
        #pragma unroll
        for (int c = 0; c < NCLS; ++c) {
            float vv = g_cs[c * H + h];
            sh    += vv;
            p_pos += vv * vv;
        }
        p_all += sh * sh;
    }
    #pragma unroll
    for (int o = 16; o > 0; o >>= 1) {
        p_all += __shfl_xor_sync(0xffffffffu, p_all, o);
        p_pos += __shfl_xor_sync(0xffffffffu, p_pos, o);
    }
    if (lane == 0) { sredA[warp] = p_all; sredP[warp] = p_pos; }
    __syncthreads();

    if (tid == 0) {
        float A = 0.0f, P = 0.0f;
        #pragma unroll
        for (int w = 0; w < 16; ++w) { A += sredA[w]; P += sredP[w]; }
        float n_pos = 0.0f;
        #pragma unroll
        for (int c = 0; c < NCLS; ++c) {
            float nc = (float)g_cnt_tot[c];
            n_pos += nc * nc;
        }
        float Nf    = (float)N;
        float n_neg = Nf * Nf - n_pos;

        float pos_mean = (P / TEMPERATURE) / n_pos;
        float neg_mean = ((A - P) / TEMPERATURE) / n_neg;
        float d = neg_mean - pos_mean;
        loss_sh = (d > 0.0f) ? d + log1pf(expf(-d)) : log1pf(expf(d));
    }
    __syncthreads();
    for (int i = tid; i < out_size; i += TPB) out[i] = loss_sh;

    // Self-clean for the next graph replay.
    for (int i = tid; i < CH; i += TPB) g_cs[i] = 0.0f;
    if (tid < NCLS) g_cnt_tot[tid] = 0;
    if (tid == 0)   g_done = 0u;
}

// ---------------------------------------------------------------------------
extern "C" void kernel_launch(void* const* d_in, const int* in_sizes, int n_in,
                              void* d_out, int out_size)
{
    const float* feat   = (const float*)d_in[0];
    const int*   labels = (const int*)d_in[1];
    float*       out    = (float*)d_out;
    const int N = in_sizes[1];   // 8192

    supcon_all<<<NBLK, TPB>>>(feat, labels, out, out_size, N);
}